// round 7
// baseline (speedup 1.0000x reference)
#include <cuda_runtime.h>
#include <cuda_fp16.h>
#include <cstdint>

// ===========================================================================
// Model_55611236549533 — sm_103a, fp16 mma.m16n8k16 + ldmatrix, 2 CTAs/SM.
//   Per 64-row tile (296 persistent CTAs, 8 warps):
//     L0: X[64x64]h @ W0[64x256]h (bias in acc, relu) -> H fp16
//     L1: H @ W1[128x32 per branch]h (bias in acc)
//     uniform-segment tile: reg-space shfl reduce -> atomics (fast path)
//     boundary tile: relu -> Gs fp16 -> 256-thread sorted-run reduce (slow)
// ===========================================================================

#define F_IN   64
#define S_SEG  16384
#define TILE   64
#define BLK    256
#define GRID_A 296

// strides (bytes)
#define LDW0B 144
#define LDW1B 272
#define LDXB  144
#define LDHB  528
#define LDGB  144

// smem byte offsets (16B aligned)
#define O_W0   0                 // 256*144 = 36864
#define O_W1   36864             // 64*272  = 17408
#define O_X    54272             // 64*144  =  9216
#define O_H    63488             // 64*528  = 33792
#define O_GS   97280             // 64*144  =  9216
#define O_B0   106496            // 256 f32 =  1024
#define O_B1   107520            // 64 f32  =   256
#define O_SID  107776            // 128 int =   512
#define SMEM_BYTES 108288

__device__ float g_segbuf[S_SEG * 64];   // [seg][0:32 tfc | 32:64 rl]

// ---------------------------------------------------------------- PTX utils
__device__ __forceinline__ uint32_t smem_u32(const void* p) {
    uint32_t a;
    asm("{ .reg .u64 t; cvta.to.shared.u64 t, %1; cvt.u32.u64 %0, t; }"
        : "=r"(a) : "l"(p));
    return a;
}
__device__ __forceinline__ uint32_t h2u(__half2 h) {
    return *reinterpret_cast<uint32_t*>(&h);
}
__device__ __forceinline__ void ldmx4(uint32_t* r, uint32_t addr) {
    asm volatile("ldmatrix.sync.aligned.m8n8.x4.shared.b16 {%0,%1,%2,%3}, [%4];"
                 : "=r"(r[0]), "=r"(r[1]), "=r"(r[2]), "=r"(r[3]) : "r"(addr));
}
__device__ __forceinline__ void ldmx2(uint32_t* r, uint32_t addr) {
    asm volatile("ldmatrix.sync.aligned.m8n8.x2.shared.b16 {%0,%1}, [%2];"
                 : "=r"(r[0]), "=r"(r[1]) : "r"(addr));
}
__device__ __forceinline__ void mma_f16(float* d, const uint32_t* a,
                                        const uint32_t* b) {
    asm volatile(
        "mma.sync.aligned.m16n8k16.row.col.f32.f16.f16.f32 "
        "{%0,%1,%2,%3}, {%4,%5,%6,%7}, {%8,%9}, {%0,%1,%2,%3};"
        : "+f"(d[0]), "+f"(d[1]), "+f"(d[2]), "+f"(d[3])
        : "r"(a[0]), "r"(a[1]), "r"(a[2]), "r"(a[3]), "r"(b[0]), "r"(b[1]));
}

// ------------------------------------------------------------ zero segbuf
__global__ void zero_kernel(int n4) {
    int i = blockIdx.x * blockDim.x + threadIdx.x;
    if (i < n4)
        reinterpret_cast<float4*>(g_segbuf)[i] = make_float4(0.f, 0.f, 0.f, 0.f);
}

// -------------------------------------------------------------- phase A
__global__ __launch_bounds__(BLK, 2)
void phaseA_mma(const float* __restrict__ x,
                const int*   __restrict__ seg_ids,
                const float* __restrict__ tfc0_w, const float* __restrict__ tfc0_b,
                const float* __restrict__ tfc1_w, const float* __restrict__ tfc1_b,
                const float* __restrict__ rl0_w,  const float* __restrict__ rl0_b,
                const float* __restrict__ rl1_w,  const float* __restrict__ rl1_b,
                int N)
{
    extern __shared__ char smc[];
    __half* W0s = (__half*)(smc + O_W0);
    __half* W1s = (__half*)(smc + O_W1);
    __half* Hs  = (__half*)(smc + O_H);
    float*  B0s = (float*)(smc + O_B0);
    float*  B1s = (float*)(smc + O_B1);
    int*    sid_s = (int*)(smc + O_SID);
    const uint32_t smb = smem_u32(smc);

    const int tid  = threadIdx.x;
    const int wid  = tid >> 5;
    const int lane = tid & 31;
    const int lg   = lane >> 2;       // d-frag row group
    const int lt   = lane & 3;        // d-frag col pair

    // ---- stage weights ([n][k] fp16) + biases ----
    for (int i = tid; i < 64 * 128; i += BLK) {
        int k = i >> 7, n = i & 127;
        W0s[n * 72 + k]         = __float2half_rn(tfc0_w[i]);
        W0s[(n + 128) * 72 + k] = __float2half_rn(rl0_w[i]);
    }
    for (int i = tid; i < 128 * 32; i += BLK) {
        int k = i >> 5, n = i & 31;
        W1s[n * 136 + k]        = __float2half_rn(tfc1_w[i]);
        W1s[(32 + n) * 136 + k] = __float2half_rn(rl1_w[i]);
    }
    if (tid < 128) { B0s[tid] = tfc0_b[tid]; B0s[128 + tid] = rl0_b[tid]; }
    if (tid < 32)  { B1s[tid] = tfc1_b[tid]; B1s[32 + tid] = rl1_b[tid]; }

    const int ntiles = (N + TILE - 1) / TILE;

    // ---- stage first X tile + sids ----
    int tile = blockIdx.x;
    {
        int r = tid >> 2, q = (tid & 3) * 16;
        long g = (long)tile * TILE + r;
        bool ok = (tile < ntiles) && (g < N);
        float4 v0 = make_float4(0.f,0.f,0.f,0.f), v1 = v0, v2 = v0, v3 = v0;
        if (ok) {
            const float4* xp = reinterpret_cast<const float4*>(&x[g * F_IN + q]);
            v0 = xp[0]; v1 = xp[1]; v2 = xp[2]; v3 = xp[3];
        }
        uint32_t h0 = h2u(__floats2half2_rn(v0.x, v0.y));
        uint32_t h1 = h2u(__floats2half2_rn(v0.z, v0.w));
        uint32_t h2 = h2u(__floats2half2_rn(v1.x, v1.y));
        uint32_t h3 = h2u(__floats2half2_rn(v1.z, v1.w));
        uint32_t h4 = h2u(__floats2half2_rn(v2.x, v2.y));
        uint32_t h5 = h2u(__floats2half2_rn(v2.z, v2.w));
        uint32_t h6 = h2u(__floats2half2_rn(v3.x, v3.y));
        uint32_t h7 = h2u(__floats2half2_rn(v3.z, v3.w));
        uint32_t base = smb + O_X + r * LDXB + q * 2;
        asm volatile("st.shared.v4.b32 [%0], {%1,%2,%3,%4};" ::
            "r"(base), "r"(h0), "r"(h1), "r"(h2), "r"(h3));
        asm volatile("st.shared.v4.b32 [%0], {%1,%2,%3,%4};" ::
            "r"(base + 16), "r"(h4), "r"(h5), "r"(h6), "r"(h7));
        if (tid < TILE) {
            long gi = (long)tile * TILE + tid;
            sid_s[tid] = (tile < ntiles && gi < N) ? seg_ids[gi] : -1;
        }
    }
    __syncthreads();

    // ---- warp roles ----
    const int mh0 = wid & 1;          // L0 row half
    const int no  = wid >> 1;         // L0 col octet
    const int br  = wid >> 2;         // L1 branch
    const int mh1 = wid & 1;          // L1 row half
    const int nq  = (wid >> 1) & 1;   // L1 col quarter

    // ---- preload W1 B-fragments (32 regs) ----
    uint32_t bw1[2][8][2];
    #pragma unroll
    for (int jn = 0; jn < 2; ++jn)
        #pragma unroll
        for (int kk = 0; kk < 8; ++kk) {
            int n = br * 32 + nq * 16 + jn * 8 + (lane & 7);
            int k = kk * 16 + ((lane >> 3) & 1) * 8;
            ldmx2(bw1[jn][kk], smb + O_W1 + n * LDW1B + k * 2);
        }

    int p = 0;
    for (; tile < ntiles; tile += GRID_A) {
        const int valid = min(TILE, N - tile * TILE);
        const int ntile = tile + GRID_A;

        // ---- prefetch next tile ----
        float4 px[4];
        int    psid = -1;
        {
            int r = tid >> 2, q = (tid & 3) * 16;
            long g = (long)ntile * TILE + r;
            bool ok = (ntile < ntiles) && (g < N);
            #pragma unroll
            for (int i = 0; i < 4; ++i) {
                px[i] = make_float4(0.f, 0.f, 0.f, 0.f);
                if (ok) px[i] = *reinterpret_cast<const float4*>(
                            &x[g * F_IN + q + i * 4]);
            }
            long gi = (long)ntile * TILE + tid;
            if (tid < TILE && ntile < ntiles && gi < N) psid = seg_ids[gi];
        }

        // uniform-segment flag for this tile (sorted ids: ends equal => all equal)
        const int sid_first = sid_s[p * TILE];
        const bool boundary = (sid_first != sid_s[p * TILE + TILE - 1]);

        // =============== Layer 0 (two 32-col halves) ===============
        #pragma unroll
        for (int nh = 0; nh < 2; ++nh) {
            const int cb = no * 64 + nh * 32;
            float acc[2][4][4];
            #pragma unroll
            for (int j = 0; j < 4; ++j) {
                float2 bv = *reinterpret_cast<const float2*>(&B0s[cb + j * 8 + 2 * lt]);
                #pragma unroll
                for (int m = 0; m < 2; ++m) {
                    acc[m][j][0] = bv.x; acc[m][j][1] = bv.y;
                    acc[m][j][2] = bv.x; acc[m][j][3] = bv.y;
                }
            }
            #pragma unroll
            for (int k2 = 0; k2 < 4; ++k2) {
                uint32_t a[2][4];
                #pragma unroll
                for (int m = 0; m < 2; ++m) {
                    int row = mh0 * 32 + m * 16 + (lane & 15);
                    int kc  = k2 * 16 + ((lane >> 4) << 3);
                    ldmx4(a[m], smb + O_X + row * LDXB + kc * 2);
                }
                #pragma unroll
                for (int j = 0; j < 4; ++j) {
                    uint32_t b[2];
                    int n = cb + j * 8 + (lane & 7);
                    int k = k2 * 16 + ((lane >> 3) & 1) * 8;
                    ldmx2(b, smb + O_W0 + n * LDW0B + k * 2);
                    mma_f16(acc[0][j], a[0], b);
                    mma_f16(acc[1][j], a[1], b);
                }
            }
            // relu + pack -> H fp16
            const __half2 z2 = __float2half2_rn(0.f);
            #pragma unroll
            for (int j = 0; j < 4; ++j) {
                int col = cb + j * 8 + 2 * lt;
                #pragma unroll
                for (int m = 0; m < 2; ++m) {
                    int row = mh0 * 32 + m * 16 + lg;
                    __half2 lo = __hmax2(__floats2half2_rn(acc[m][j][0], acc[m][j][1]), z2);
                    __half2 hi = __hmax2(__floats2half2_rn(acc[m][j][2], acc[m][j][3]), z2);
                    *reinterpret_cast<__half2*>((char*)Hs + row * LDHB + col * 2) = lo;
                    *reinterpret_cast<__half2*>((char*)Hs + (row + 8) * LDHB + col * 2) = hi;
                }
            }
        }
        __syncthreads();

        // ---- store prefetched X + sid (Xs free after L0) ----
        {
            int r = tid >> 2, q = (tid & 3) * 16;
            uint32_t h0 = h2u(__floats2half2_rn(px[0].x, px[0].y));
            uint32_t h1 = h2u(__floats2half2_rn(px[0].z, px[0].w));
            uint32_t h2 = h2u(__floats2half2_rn(px[1].x, px[1].y));
            uint32_t h3 = h2u(__floats2half2_rn(px[1].z, px[1].w));
            uint32_t h4 = h2u(__floats2half2_rn(px[2].x, px[2].y));
            uint32_t h5 = h2u(__floats2half2_rn(px[2].z, px[2].w));
            uint32_t h6 = h2u(__floats2half2_rn(px[3].x, px[3].y));
            uint32_t h7 = h2u(__floats2half2_rn(px[3].z, px[3].w));
            uint32_t base = smb + O_X + r * LDXB + q * 2;
            asm volatile("st.shared.v4.b32 [%0], {%1,%2,%3,%4};" ::
                "r"(base), "r"(h0), "r"(h1), "r"(h2), "r"(h3));
            asm volatile("st.shared.v4.b32 [%0], {%1,%2,%3,%4};" ::
                "r"(base + 16), "r"(h4), "r"(h5), "r"(h6), "r"(h7));
            if (tid < TILE) sid_s[(p ^ 1) * TILE + tid] = psid;
        }

        // =============== Layer 1 ===============
        {
            float acc[2][2][4];
            #pragma unroll
            for (int jn = 0; jn < 2; ++jn) {
                int col = br * 32 + nq * 16 + jn * 8 + 2 * lt;
                float2 bv = *reinterpret_cast<const float2*>(&B1s[col]);
                #pragma unroll
                for (int m = 0; m < 2; ++m) {
                    acc[m][jn][0] = bv.x; acc[m][jn][1] = bv.y;
                    acc[m][jn][2] = bv.x; acc[m][jn][3] = bv.y;
                }
            }
            #pragma unroll
            for (int kk = 0; kk < 8; ++kk) {
                uint32_t a[2][4];
                #pragma unroll
                for (int m = 0; m < 2; ++m) {
                    int row = mh1 * 32 + m * 16 + (lane & 15);
                    int kc  = br * 128 + kk * 16 + ((lane >> 4) << 3);
                    ldmx4(a[m], smb + O_H + row * LDHB + kc * 2);
                }
                #pragma unroll
                for (int jn = 0; jn < 2; ++jn) {
                    mma_f16(acc[0][jn], a[0], bw1[jn][kk]);
                    mma_f16(acc[1][jn], a[1], bw1[jn][kk]);
                }
            }

            if (!boundary) {
                // ---- FAST PATH: whole tile is one segment. relu + sum the
                // warp's 64 rows directly from registers; 3-step shfl over
                // row groups; 4 lanes issue atomics (overlaps next barrier).
                #pragma unroll
                for (int jn = 0; jn < 2; ++jn) {
                    float s0 = fmaxf(acc[0][jn][0], 0.f) + fmaxf(acc[0][jn][2], 0.f)
                             + fmaxf(acc[1][jn][0], 0.f) + fmaxf(acc[1][jn][2], 0.f);
                    float s1 = fmaxf(acc[0][jn][1], 0.f) + fmaxf(acc[0][jn][3], 0.f)
                             + fmaxf(acc[1][jn][1], 0.f) + fmaxf(acc[1][jn][3], 0.f);
                    #pragma unroll
                    for (int o = 4; o < 32; o <<= 1) {
                        s0 += __shfl_xor_sync(0xffffffffu, s0, o);
                        s1 += __shfl_xor_sync(0xffffffffu, s1, o);
                    }
                    if (lg == 0) {
                        int col = br * 32 + nq * 16 + jn * 8 + 2 * lt;
                        atomicAdd(&g_segbuf[sid_first * 64 + col], s0);
                        atomicAdd(&g_segbuf[sid_first * 64 + col + 1], s1);
                    }
                }
            } else {
                // ---- SLOW PATH: relu + pack -> Gs fp16 for run reduction.
                const __half2 z2 = __float2half2_rn(0.f);
                #pragma unroll
                for (int jn = 0; jn < 2; ++jn) {
                    int col = br * 32 + nq * 16 + jn * 8 + 2 * lt;
                    #pragma unroll
                    for (int m = 0; m < 2; ++m) {
                        int row = mh1 * 32 + m * 16 + lg;
                        __half2 lo = __hmax2(__floats2half2_rn(acc[m][jn][0], acc[m][jn][1]), z2);
                        __half2 hi = __hmax2(__floats2half2_rn(acc[m][jn][2], acc[m][jn][3]), z2);
                        *reinterpret_cast<__half2*>(smc + O_GS + row * LDGB + col * 2) = lo;
                        *reinterpret_cast<__half2*>(smc + O_GS + (row + 8) * LDGB + col * 2) = hi;
                    }
                }
            }
        }
        __syncthreads();

        // ---- sorted-run segment reduction (boundary tiles; all 256 thr) ----
        if (boundary) {
            const int cp    = tid & 31;          // col pair
            const int chunk = tid >> 5;          // 8 chunks x 8 rows
            const int rbeg = chunk * 8;
            const int rend = min(rbeg + 8, valid);
            const int* sid = &sid_s[p * TILE];
            if (rbeg < rend) {
                int prev = sid[rbeg];
                float rx = 0.f, ry = 0.f;
                for (int r = rbeg; r < rend; ++r) {
                    int sd = sid[r];
                    if (sd != prev) {
                        atomicAdd(&g_segbuf[prev * 64 + 2 * cp], rx);
                        atomicAdd(&g_segbuf[prev * 64 + 2 * cp + 1], ry);
                        rx = 0.f; ry = 0.f; prev = sd;
                    }
                    __half2 h = *reinterpret_cast<const __half2*>(
                        smc + O_GS + r * LDGB + cp * 4);
                    float2 f = __half22float2(h);
                    rx += f.x; ry += f.y;
                }
                atomicAdd(&g_segbuf[prev * 64 + 2 * cp], rx);
                atomicAdd(&g_segbuf[prev * 64 + 2 * cp + 1], ry);
            }
        }
        p ^= 1;
    }
}

// ---------------------------------------------------------------- phase B
__global__ __launch_bounds__(256)
void phaseB_kernel(const float* __restrict__ fwd0_w, const float* __restrict__ fwd0_b,
                   const float* __restrict__ fwd1_w, const float* __restrict__ fwd1_b,
                   const float* __restrict__ com0_w, const float* __restrict__ com0_b,
                   const float* __restrict__ com1_w, const float* __restrict__ com1_b,
                   const float* __restrict__ bwd0_w, const float* __restrict__ bwd0_b,
                   const float* __restrict__ bwd1_w, const float* __restrict__ bwd1_b,
                   const float* __restrict__ cost0_w, const float* __restrict__ cost0_b,
                   const float* __restrict__ cost1_w, const float* __restrict__ cost1_b,
                   const float* __restrict__ pol_w,   const float* __restrict__ pol_b,
                   float* __restrict__ out, int S)
{
    __shared__ float s_f0[32 * 64], s_c0[32 * 64], s_b0[32 * 64];
    __shared__ float s_f0b[64], s_c0b[64], s_b0b[64];
    __shared__ float s_f1[64], s_c1[64], s_b1[64];
    __shared__ float s_k0[3 * 64], s_k0b[64];
    __shared__ float s_k1[64 * 32], s_k1b[32];
    __shared__ float s_pol[64];
    __shared__ float s_scal[4];

    const int t = threadIdx.x;
    for (int i = t; i < 32 * 64; i += 256) {
        s_f0[i] = fwd0_w[i]; s_c0[i] = com0_w[i]; s_b0[i] = bwd0_w[i];
    }
    for (int i = t; i < 64 * 32; i += 256) s_k1[i] = cost1_w[i];
    if (t < 64) {
        s_f0b[t] = fwd0_b[t]; s_c0b[t] = com0_b[t]; s_b0b[t] = bwd0_b[t];
        s_f1[t] = fwd1_w[t];  s_c1[t] = com1_w[t];  s_b1[t] = bwd1_w[t];
        s_k0b[t] = cost0_b[t]; s_pol[t] = pol_w[t];
    }
    if (t < 3 * 64) s_k0[t] = cost0_w[t];
    if (t < 32) s_k1b[t] = cost1_b[t];
    if (t == 0) {
        s_scal[0] = fwd1_b[0]; s_scal[1] = com1_b[0];
        s_scal[2] = bwd1_b[0]; s_scal[3] = pol_b[0];
    }
    __syncthreads();

    const int l = t & 31;
    const int warp = (blockIdx.x * blockDim.x + t) >> 5;
    const int nwarps = (gridDim.x * blockDim.x) >> 5;

    for (int s = warp; s < S; s += nwarps) {
        const float st = g_segbuf[s * 64 + l];
        const float sr = g_segbuf[s * 64 + 32 + l];

        float hf0 = s_f0b[l], hf1 = s_f0b[l + 32];
        float hc0 = s_c0b[l], hc1 = s_c0b[l + 32];
        float hb0 = s_b0b[l], hb1 = s_b0b[l + 32];
        #pragma unroll
        for (int k = 0; k < 32; ++k) {
            float sk = __shfl_sync(0xffffffffu, st, k);
            hf0 = fmaf(sk, s_f0[k * 64 + l],      hf0);
            hf1 = fmaf(sk, s_f0[k * 64 + l + 32], hf1);
            hc0 = fmaf(sk, s_c0[k * 64 + l],      hc0);
            hc1 = fmaf(sk, s_c0[k * 64 + l + 32], hc1);
            hb0 = fmaf(sk, s_b0[k * 64 + l],      hb0);
            hb1 = fmaf(sk, s_b0[k * 64 + l + 32], hb1);
        }
        float vf = fmaxf(hf0, 0.f) * s_f1[l] + fmaxf(hf1, 0.f) * s_f1[l + 32];
        float vc = fmaxf(hc0, 0.f) * s_c1[l] + fmaxf(hc1, 0.f) * s_c1[l + 32];
        float vb = fmaxf(hb0, 0.f) * s_b1[l] + fmaxf(hb1, 0.f) * s_b1[l + 32];
        #pragma unroll
        for (int o = 16; o > 0; o >>= 1) {
            vf += __shfl_xor_sync(0xffffffffu, vf, o);
            vc += __shfl_xor_sync(0xffffffffu, vc, o);
            vb += __shfl_xor_sync(0xffffffffu, vb, o);
        }
        const float fwd = vf + s_scal[0];
        const float com = vc + s_scal[1];
        const float bwd = vb + s_scal[2];

        float c1a = fmaf(fwd, s_k0[l],
                    fmaf(com, s_k0[64 + l],
                    fmaf(bwd, s_k0[128 + l], s_k0b[l])));
        float c1b = fmaf(fwd, s_k0[l + 32],
                    fmaf(com, s_k0[64 + l + 32],
                    fmaf(bwd, s_k0[128 + l + 32], s_k0b[l + 32])));
        c1a = fmaxf(c1a, 0.f);
        c1b = fmaxf(c1b, 0.f);

        float c2 = s_k1b[l];
        #pragma unroll
        for (int jj = 0; jj < 32; ++jj) {
            float a = __shfl_sync(0xffffffffu, c1a, jj);
            float b = __shfl_sync(0xffffffffu, c1b, jj);
            c2 = fmaf(a, s_k1[jj * 32 + l], c2);
            c2 = fmaf(b, s_k1[(jj + 32) * 32 + l], c2);
        }
        c2 = fmaxf(c2, 0.f);

        float v = fmaf(sr, s_pol[l], c2 * s_pol[l + 32]);
        #pragma unroll
        for (int o = 16; o > 0; o >>= 1)
            v += __shfl_xor_sync(0xffffffffu, v, o);
        if (l == 0) out[s] = v + s_scal[3];
    }
}

// ----------------------------------------------------------------- launch
extern "C" void kernel_launch(void* const* d_in, const int* in_sizes, int n_in,
                              void* d_out, int out_size)
{
    const float* x      = (const float*)d_in[0];
    const int*   sid    = (const int*)  d_in[1];
    const float* tfc0_w = (const float*)d_in[4];
    const float* tfc0_b = (const float*)d_in[5];
    const float* tfc1_w = (const float*)d_in[6];
    const float* tfc1_b = (const float*)d_in[7];
    const float* fwd0_w = (const float*)d_in[8];
    const float* fwd0_b = (const float*)d_in[9];
    const float* fwd1_w = (const float*)d_in[10];
    const float* fwd1_b = (const float*)d_in[11];
    const float* com0_w = (const float*)d_in[12];
    const float* com0_b = (const float*)d_in[13];
    const float* com1_w = (const float*)d_in[14];
    const float* com1_b = (const float*)d_in[15];
    const float* bwd0_w = (const float*)d_in[16];
    const float* bwd0_b = (const float*)d_in[17];
    const float* bwd1_w = (const float*)d_in[18];
    const float* bwd1_b = (const float*)d_in[19];
    const float* rl0_w  = (const float*)d_in[20];
    const float* rl0_b  = (const float*)d_in[21];
    const float* rl1_w  = (const float*)d_in[22];
    const float* rl1_b  = (const float*)d_in[23];
    const float* cost0_w = (const float*)d_in[24];
    const float* cost0_b = (const float*)d_in[25];
    const float* cost1_w = (const float*)d_in[26];
    const float* cost1_b = (const float*)d_in[27];
    const float* pol_w   = (const float*)d_in[28];
    const float* pol_b   = (const float*)d_in[29];

    const int N = in_sizes[0] / F_IN;
    const int S = out_size;

    static int configured = 0;
    if (!configured) {
        cudaFuncSetAttribute(phaseA_mma,
                             cudaFuncAttributeMaxDynamicSharedMemorySize,
                             SMEM_BYTES);
        configured = 1;
    }

    {
        int n4 = (S_SEG * 64) / 4;
        zero_kernel<<<(n4 + 255) / 256, 256>>>(n4);
    }

    phaseA_mma<<<GRID_A, BLK, SMEM_BYTES>>>(
        x, sid, tfc0_w, tfc0_b, tfc1_w, tfc1_b,
        rl0_w, rl0_b, rl1_w, rl1_b, N);

    phaseB_kernel<<<128, 256>>>(
        fwd0_w, fwd0_b, fwd1_w, fwd1_b,
        com0_w, com0_b, com1_w, com1_b,
        bwd0_w, bwd0_b, bwd1_w, bwd1_b,
        cost0_w, cost0_b, cost1_w, cost1_b,
        pol_w, pol_b,
        (float*)d_out, S);
}

// round 8
// speedup vs baseline: 1.0696x; 1.0696x over previous
#include <cuda_runtime.h>
#include <cuda_fp16.h>
#include <cstdint>

// ===========================================================================
// Model_55611236549533 — sm_103a, fp16 mma.m16n8k16 + ldmatrix, 2 CTAs/SM.
//   Per 64-row tile (296 persistent CTAs, 8 warps):
//     L0: X[64x64]h @ W0[64x256]h, merged cols, paired-B ldmx4 -> H fp16
//     L1: H @ W1[128x32 per branch]h (bias in acc, relu) -> Gs fp16
//     warps 0-3: sorted-run segment reduce (half2) -> atomics
// ===========================================================================

#define F_IN   64
#define S_SEG  16384
#define TILE   64
#define BLK    256
#define GRID_A 296

// strides (bytes)
#define LDW0B 144
#define LDW1B 272
#define LDXB  144
#define LDHB  528
#define LDGB  144

// smem byte offsets (16B aligned)
#define O_W0   0                 // 256*144 = 36864
#define O_W1   36864             // 64*272  = 17408
#define O_X    54272             // 64*144  =  9216
#define O_H    63488             // 64*528  = 33792
#define O_GS   97280             // 64*144  =  9216
#define O_B0   106496            // 256 f32 =  1024
#define O_B1   107520            // 64 f32  =   256
#define O_SID  107776            // 128 int =   512
#define SMEM_BYTES 108288

__device__ float g_segbuf[S_SEG * 64];   // [seg][0:32 tfc | 32:64 rl]

// ---------------------------------------------------------------- PTX utils
__device__ __forceinline__ uint32_t smem_u32(const void* p) {
    uint32_t a;
    asm("{ .reg .u64 t; cvta.to.shared.u64 t, %1; cvt.u32.u64 %0, t; }"
        : "=r"(a) : "l"(p));
    return a;
}
__device__ __forceinline__ uint32_t h2u(__half2 h) {
    return *reinterpret_cast<uint32_t*>(&h);
}
__device__ __forceinline__ void ldmx4(uint32_t* r, uint32_t addr) {
    asm volatile("ldmatrix.sync.aligned.m8n8.x4.shared.b16 {%0,%1,%2,%3}, [%4];"
                 : "=r"(r[0]), "=r"(r[1]), "=r"(r[2]), "=r"(r[3]) : "r"(addr));
}
__device__ __forceinline__ void ldmx2(uint32_t* r, uint32_t addr) {
    asm volatile("ldmatrix.sync.aligned.m8n8.x2.shared.b16 {%0,%1}, [%2];"
                 : "=r"(r[0]), "=r"(r[1]) : "r"(addr));
}
__device__ __forceinline__ void mma_f16(float* d, const uint32_t* a,
                                        const uint32_t* b) {
    asm volatile(
        "mma.sync.aligned.m16n8k16.row.col.f32.f16.f16.f32 "
        "{%0,%1,%2,%3}, {%4,%5,%6,%7}, {%8,%9}, {%0,%1,%2,%3};"
        : "+f"(d[0]), "+f"(d[1]), "+f"(d[2]), "+f"(d[3])
        : "r"(a[0]), "r"(a[1]), "r"(a[2]), "r"(a[3]), "r"(b[0]), "r"(b[1]));
}

// ------------------------------------------------------------ zero segbuf
__global__ void zero_kernel(int n4) {
    int i = blockIdx.x * blockDim.x + threadIdx.x;
    if (i < n4)
        reinterpret_cast<float4*>(g_segbuf)[i] = make_float4(0.f, 0.f, 0.f, 0.f);
}

// -------------------------------------------------------------- phase A
__global__ __launch_bounds__(BLK, 2)
void phaseA_mma(const float* __restrict__ x,
                const int*   __restrict__ seg_ids,
                const float* __restrict__ tfc0_w, const float* __restrict__ tfc0_b,
                const float* __restrict__ tfc1_w, const float* __restrict__ tfc1_b,
                const float* __restrict__ rl0_w,  const float* __restrict__ rl0_b,
                const float* __restrict__ rl1_w,  const float* __restrict__ rl1_b,
                int N)
{
    extern __shared__ char smc[];
    __half* W0s = (__half*)(smc + O_W0);
    __half* W1s = (__half*)(smc + O_W1);
    __half* Hs  = (__half*)(smc + O_H);
    float*  B0s = (float*)(smc + O_B0);
    float*  B1s = (float*)(smc + O_B1);
    int*    sid_s = (int*)(smc + O_SID);
    const uint32_t smb = smem_u32(smc);

    const int tid  = threadIdx.x;
    const int wid  = tid >> 5;
    const int lane = tid & 31;
    const int lg   = lane >> 2;       // d-frag row group
    const int lt   = lane & 3;        // d-frag col pair

    // ---- stage weights ([n][k] fp16) + biases ----
    for (int i = tid; i < 64 * 128; i += BLK) {
        int k = i >> 7, n = i & 127;
        W0s[n * 72 + k]         = __float2half_rn(tfc0_w[i]);
        W0s[(n + 128) * 72 + k] = __float2half_rn(rl0_w[i]);
    }
    for (int i = tid; i < 128 * 32; i += BLK) {
        int k = i >> 5, n = i & 31;
        W1s[n * 136 + k]        = __float2half_rn(tfc1_w[i]);
        W1s[(32 + n) * 136 + k] = __float2half_rn(rl1_w[i]);
    }
    if (tid < 128) { B0s[tid] = tfc0_b[tid]; B0s[128 + tid] = rl0_b[tid]; }
    if (tid < 32)  { B1s[tid] = tfc1_b[tid]; B1s[32 + tid] = rl1_b[tid]; }

    const int ntiles = (N + TILE - 1) / TILE;

    // ---- stage first X tile + sids ----
    int tile = blockIdx.x;
    {
        int r = tid >> 2, q = (tid & 3) * 16;
        long g = (long)tile * TILE + r;
        bool ok = (tile < ntiles) && (g < N);
        float4 v0 = make_float4(0.f,0.f,0.f,0.f), v1 = v0, v2 = v0, v3 = v0;
        if (ok) {
            const float4* xp = reinterpret_cast<const float4*>(&x[g * F_IN + q]);
            v0 = xp[0]; v1 = xp[1]; v2 = xp[2]; v3 = xp[3];
        }
        uint32_t h0 = h2u(__floats2half2_rn(v0.x, v0.y));
        uint32_t h1 = h2u(__floats2half2_rn(v0.z, v0.w));
        uint32_t h2 = h2u(__floats2half2_rn(v1.x, v1.y));
        uint32_t h3 = h2u(__floats2half2_rn(v1.z, v1.w));
        uint32_t h4 = h2u(__floats2half2_rn(v2.x, v2.y));
        uint32_t h5 = h2u(__floats2half2_rn(v2.z, v2.w));
        uint32_t h6 = h2u(__floats2half2_rn(v3.x, v3.y));
        uint32_t h7 = h2u(__floats2half2_rn(v3.z, v3.w));
        uint32_t base = smb + O_X + r * LDXB + q * 2;
        asm volatile("st.shared.v4.b32 [%0], {%1,%2,%3,%4};" ::
            "r"(base), "r"(h0), "r"(h1), "r"(h2), "r"(h3));
        asm volatile("st.shared.v4.b32 [%0], {%1,%2,%3,%4};" ::
            "r"(base + 16), "r"(h4), "r"(h5), "r"(h6), "r"(h7));
        if (tid < TILE) {
            long gi = (long)tile * TILE + tid;
            sid_s[tid] = (tile < ntiles && gi < N) ? seg_ids[gi] : -1;
        }
    }
    __syncthreads();

    // ---- warp roles ----
    const int mh0 = wid & 1;          // L0 row half
    const int no  = wid >> 1;         // L0 col octet
    const int br  = wid >> 2;         // L1 branch
    const int mh1 = wid & 1;          // L1 row half
    const int nq  = (wid >> 1) & 1;   // L1 col quarter

    // ---- preload W1 B-fragments (32 regs) ----
    uint32_t bw1[2][8][2];
    #pragma unroll
    for (int jn = 0; jn < 2; ++jn)
        #pragma unroll
        for (int kk = 0; kk < 8; ++kk) {
            int n = br * 32 + nq * 16 + jn * 8 + (lane & 7);
            int k = kk * 16 + ((lane >> 3) & 1) * 8;
            ldmx2(bw1[jn][kk], smb + O_W1 + n * LDW1B + k * 2);
        }

    // fragment addressing constants
    const uint32_t a0_base = smb + O_X +
        (mh0 * 32 + (lane & 15)) * LDXB + ((lane >> 4) << 3) * 2;
    const uint32_t b0_base = smb + O_W0 +
        (no * 64 + ((lane >> 4) << 3) + (lane & 7)) * LDW0B +
        (((lane >> 3) & 1) * 8) * 2;
    const uint32_t a1_base = smb + O_H +
        (mh1 * 32 + (lane & 15)) * LDHB +
        (br * 128 + ((lane >> 4) << 3)) * 2;

    int p = 0;
    for (; tile < ntiles; tile += GRID_A) {
        const int valid = min(TILE, N - tile * TILE);
        const int ntile = tile + GRID_A;

        // =============== Layer 0 (merged; paired-B ldmx4) ===============
        {
            float acc[2][8][4];
            #pragma unroll
            for (int j = 0; j < 8; ++j) {
                float2 bv = *reinterpret_cast<const float2*>(
                    &B0s[no * 64 + j * 8 + 2 * lt]);
                #pragma unroll
                for (int m = 0; m < 2; ++m) {
                    acc[m][j][0] = bv.x; acc[m][j][1] = bv.y;
                    acc[m][j][2] = bv.x; acc[m][j][3] = bv.y;
                }
            }
            #pragma unroll
            for (int k2 = 0; k2 < 4; ++k2) {
                uint32_t a[2][4];
                ldmx4(a[0], a0_base + k2 * 32);
                ldmx4(a[1], a0_base + 16 * LDXB + k2 * 32);
                #pragma unroll
                for (int jp = 0; jp < 4; ++jp) {
                    uint32_t b[4];
                    ldmx4(b, b0_base + jp * 16 * LDW0B + k2 * 32);
                    mma_f16(acc[0][2 * jp],     a[0], b);
                    mma_f16(acc[1][2 * jp],     a[1], b);
                    mma_f16(acc[0][2 * jp + 1], a[0], b + 2);
                    mma_f16(acc[1][2 * jp + 1], a[1], b + 2);
                }
            }
            // relu + pack -> H fp16
            const __half2 z2 = __float2half2_rn(0.f);
            #pragma unroll
            for (int j = 0; j < 8; ++j) {
                int col = no * 64 + j * 8 + 2 * lt;
                #pragma unroll
                for (int m = 0; m < 2; ++m) {
                    int row = mh0 * 32 + m * 16 + lg;
                    __half2 lo = __hmax2(__floats2half2_rn(acc[m][j][0], acc[m][j][1]), z2);
                    __half2 hi = __hmax2(__floats2half2_rn(acc[m][j][2], acc[m][j][3]), z2);
                    *reinterpret_cast<__half2*>((char*)Hs + row * LDHB + col * 2) = lo;
                    *reinterpret_cast<__half2*>((char*)Hs + (row + 8) * LDHB + col * 2) = hi;
                }
            }
        }

        // ---- prefetch next tile (issued after acc is dead) ----
        float4 px[4];
        int    psid = -1;
        {
            int r = tid >> 2, q = (tid & 3) * 16;
            long g = (long)ntile * TILE + r;
            bool ok = (ntile < ntiles) && (g < N);
            #pragma unroll
            for (int i = 0; i < 4; ++i) {
                px[i] = make_float4(0.f, 0.f, 0.f, 0.f);
                if (ok) px[i] = *reinterpret_cast<const float4*>(
                            &x[g * F_IN + q + i * 4]);
            }
            long gi = (long)ntile * TILE + tid;
            if (tid < TILE && ntile < ntiles && gi < N) psid = seg_ids[gi];
        }
        __syncthreads();

        // ---- store prefetched X + sid (Xs free after L0) ----
        {
            int r = tid >> 2, q = (tid & 3) * 16;
            uint32_t h0 = h2u(__floats2half2_rn(px[0].x, px[0].y));
            uint32_t h1 = h2u(__floats2half2_rn(px[0].z, px[0].w));
            uint32_t h2 = h2u(__floats2half2_rn(px[1].x, px[1].y));
            uint32_t h3 = h2u(__floats2half2_rn(px[1].z, px[1].w));
            uint32_t h4 = h2u(__floats2half2_rn(px[2].x, px[2].y));
            uint32_t h5 = h2u(__floats2half2_rn(px[2].z, px[2].w));
            uint32_t h6 = h2u(__floats2half2_rn(px[3].x, px[3].y));
            uint32_t h7 = h2u(__floats2half2_rn(px[3].z, px[3].w));
            uint32_t base = smb + O_X + r * LDXB + q * 2;
            asm volatile("st.shared.v4.b32 [%0], {%1,%2,%3,%4};" ::
                "r"(base), "r"(h0), "r"(h1), "r"(h2), "r"(h3));
            asm volatile("st.shared.v4.b32 [%0], {%1,%2,%3,%4};" ::
                "r"(base + 16), "r"(h4), "r"(h5), "r"(h6), "r"(h7));
            if (tid < TILE) sid_s[(p ^ 1) * TILE + tid] = psid;
        }

        // =============== Layer 1 ===============
        {
            float acc[2][2][4];
            #pragma unroll
            for (int jn = 0; jn < 2; ++jn) {
                int col = br * 32 + nq * 16 + jn * 8 + 2 * lt;
                float2 bv = *reinterpret_cast<const float2*>(&B1s[col]);
                #pragma unroll
                for (int m = 0; m < 2; ++m) {
                    acc[m][jn][0] = bv.x; acc[m][jn][1] = bv.y;
                    acc[m][jn][2] = bv.x; acc[m][jn][3] = bv.y;
                }
            }
            #pragma unroll
            for (int kk = 0; kk < 8; ++kk) {
                uint32_t a[2][4];
                ldmx4(a[0], a1_base + kk * 32);
                ldmx4(a[1], a1_base + 16 * LDHB + kk * 32);
                #pragma unroll
                for (int jn = 0; jn < 2; ++jn) {
                    mma_f16(acc[0][jn], a[0], bw1[jn][kk]);
                    mma_f16(acc[1][jn], a[1], bw1[jn][kk]);
                }
            }
            // relu + pack -> Gs fp16
            const __half2 z2 = __float2half2_rn(0.f);
            #pragma unroll
            for (int jn = 0; jn < 2; ++jn) {
                int col = br * 32 + nq * 16 + jn * 8 + 2 * lt;
                #pragma unroll
                for (int m = 0; m < 2; ++m) {
                    int row = mh1 * 32 + m * 16 + lg;
                    __half2 lo = __hmax2(__floats2half2_rn(acc[m][jn][0], acc[m][jn][1]), z2);
                    __half2 hi = __hmax2(__floats2half2_rn(acc[m][jn][2], acc[m][jn][3]), z2);
                    *reinterpret_cast<__half2*>(smc + O_GS + row * LDGB + col * 2) = lo;
                    *reinterpret_cast<__half2*>(smc + O_GS + (row + 8) * LDGB + col * 2) = hi;
                }
            }
        }
        __syncthreads();

        // ---- sorted-run segment reduction (warps 0-3; half2 cols) ----
        if (tid < 128) {
            const int cp    = tid & 31;          // col pair
            const int chunk = tid >> 5;          // 4 chunks x 16 rows
            const int rbeg = chunk * 16;
            const int rend = min(rbeg + 16, valid);
            const int* sid = &sid_s[p * TILE];
            if (rbeg < rend) {
                int prev = sid[rbeg];
                float rx = 0.f, ry = 0.f;
                for (int r = rbeg; r < rend; ++r) {
                    int sd = sid[r];
                    if (sd != prev) {
                        atomicAdd(&g_segbuf[prev * 64 + 2 * cp], rx);
                        atomicAdd(&g_segbuf[prev * 64 + 2 * cp + 1], ry);
                        rx = 0.f; ry = 0.f; prev = sd;
                    }
                    __half2 h = *reinterpret_cast<const __half2*>(
                        smc + O_GS + r * LDGB + cp * 4);
                    float2 f = __half22float2(h);
                    rx += f.x; ry += f.y;
                }
                atomicAdd(&g_segbuf[prev * 64 + 2 * cp], rx);
                atomicAdd(&g_segbuf[prev * 64 + 2 * cp + 1], ry);
            }
        }
        p ^= 1;
    }
}

// ---------------------------------------------------------------- phase B
__global__ __launch_bounds__(256)
void phaseB_kernel(const float* __restrict__ fwd0_w, const float* __restrict__ fwd0_b,
                   const float* __restrict__ fwd1_w, const float* __restrict__ fwd1_b,
                   const float* __restrict__ com0_w, const float* __restrict__ com0_b,
                   const float* __restrict__ com1_w, const float* __restrict__ com1_b,
                   const float* __restrict__ bwd0_w, const float* __restrict__ bwd0_b,
                   const float* __restrict__ bwd1_w, const float* __restrict__ bwd1_b,
                   const float* __restrict__ cost0_w, const float* __restrict__ cost0_b,
                   const float* __restrict__ cost1_w, const float* __restrict__ cost1_b,
                   const float* __restrict__ pol_w,   const float* __restrict__ pol_b,
                   float* __restrict__ out, int S)
{
    __shared__ float s_f0[32 * 64], s_c0[32 * 64], s_b0[32 * 64];
    __shared__ float s_f0b[64], s_c0b[64], s_b0b[64];
    __shared__ float s_f1[64], s_c1[64], s_b1[64];
    __shared__ float s_k0[3 * 64], s_k0b[64];
    __shared__ float s_k1[64 * 32], s_k1b[32];
    __shared__ float s_pol[64];
    __shared__ float s_scal[4];

    const int t = threadIdx.x;
    for (int i = t; i < 32 * 64; i += 256) {
        s_f0[i] = fwd0_w[i]; s_c0[i] = com0_w[i]; s_b0[i] = bwd0_w[i];
    }
    for (int i = t; i < 64 * 32; i += 256) s_k1[i] = cost1_w[i];
    if (t < 64) {
        s_f0b[t] = fwd0_b[t]; s_c0b[t] = com0_b[t]; s_b0b[t] = bwd0_b[t];
        s_f1[t] = fwd1_w[t];  s_c1[t] = com1_w[t];  s_b1[t] = bwd1_w[t];
        s_k0b[t] = cost0_b[t]; s_pol[t] = pol_w[t];
    }
    if (t < 3 * 64) s_k0[t] = cost0_w[t];
    if (t < 32) s_k1b[t] = cost1_b[t];
    if (t == 0) {
        s_scal[0] = fwd1_b[0]; s_scal[1] = com1_b[0];
        s_scal[2] = bwd1_b[0]; s_scal[3] = pol_b[0];
    }
    __syncthreads();

    const int l = t & 31;
    const int warp = (blockIdx.x * blockDim.x + t) >> 5;
    const int nwarps = (gridDim.x * blockDim.x) >> 5;

    for (int s = warp; s < S; s += nwarps) {
        const float st = g_segbuf[s * 64 + l];
        const float sr = g_segbuf[s * 64 + 32 + l];

        float hf0 = s_f0b[l], hf1 = s_f0b[l + 32];
        float hc0 = s_c0b[l], hc1 = s_c0b[l + 32];
        float hb0 = s_b0b[l], hb1 = s_b0b[l + 32];
        #pragma unroll
        for (int k = 0; k < 32; ++k) {
            float sk = __shfl_sync(0xffffffffu, st, k);
            hf0 = fmaf(sk, s_f0[k * 64 + l],      hf0);
            hf1 = fmaf(sk, s_f0[k * 64 + l + 32], hf1);
            hc0 = fmaf(sk, s_c0[k * 64 + l],      hc0);
            hc1 = fmaf(sk, s_c0[k * 64 + l + 32], hc1);
            hb0 = fmaf(sk, s_b0[k * 64 + l],      hb0);
            hb1 = fmaf(sk, s_b0[k * 64 + l + 32], hb1);
        }
        float vf = fmaxf(hf0, 0.f) * s_f1[l] + fmaxf(hf1, 0.f) * s_f1[l + 32];
        float vc = fmaxf(hc0, 0.f) * s_c1[l] + fmaxf(hc1, 0.f) * s_c1[l + 32];
        float vb = fmaxf(hb0, 0.f) * s_b1[l] + fmaxf(hb1, 0.f) * s_b1[l + 32];
        #pragma unroll
        for (int o = 16; o > 0; o >>= 1) {
            vf += __shfl_xor_sync(0xffffffffu, vf, o);
            vc += __shfl_xor_sync(0xffffffffu, vc, o);
            vb += __shfl_xor_sync(0xffffffffu, vb, o);
        }
        const float fwd = vf + s_scal[0];
        const float com = vc + s_scal[1];
        const float bwd = vb + s_scal[2];

        float c1a = fmaf(fwd, s_k0[l],
                    fmaf(com, s_k0[64 + l],
                    fmaf(bwd, s_k0[128 + l], s_k0b[l])));
        float c1b = fmaf(fwd, s_k0[l + 32],
                    fmaf(com, s_k0[64 + l + 32],
                    fmaf(bwd, s_k0[128 + l + 32], s_k0b[l + 32])));
        c1a = fmaxf(c1a, 0.f);
        c1b = fmaxf(c1b, 0.f);

        float c2 = s_k1b[l];
        #pragma unroll
        for (int jj = 0; jj < 32; ++jj) {
            float a = __shfl_sync(0xffffffffu, c1a, jj);
            float b = __shfl_sync(0xffffffffu, c1b, jj);
            c2 = fmaf(a, s_k1[jj * 32 + l], c2);
            c2 = fmaf(b, s_k1[(jj + 32) * 32 + l], c2);
        }
        c2 = fmaxf(c2, 0.f);

        float v = fmaf(sr, s_pol[l], c2 * s_pol[l + 32]);
        #pragma unroll
        for (int o = 16; o > 0; o >>= 1)
            v += __shfl_xor_sync(0xffffffffu, v, o);
        if (l == 0) out[s] = v + s_scal[3];
    }
}

// ----------------------------------------------------------------- launch
extern "C" void kernel_launch(void* const* d_in, const int* in_sizes, int n_in,
                              void* d_out, int out_size)
{
    const float* x      = (const float*)d_in[0];
    const int*   sid    = (const int*)  d_in[1];
    const float* tfc0_w = (const float*)d_in[4];
    const float* tfc0_b = (const float*)d_in[5];
    const float* tfc1_w = (const float*)d_in[6];
    const float* tfc1_b = (const float*)d_in[7];
    const float* fwd0_w = (const float*)d_in[8];
    const float* fwd0_b = (const float*)d_in[9];
    const float* fwd1_w = (const float*)d_in[10];
    const float* fwd1_b = (const float*)d_in[11];
    const float* com0_w = (const float*)d_in[12];
    const float* com0_b = (const float*)d_in[13];
    const float* com1_w = (const float*)d_in[14];
    const float* com1_b = (const float*)d_in[15];
    const float* bwd0_w = (const float*)d_in[16];
    const float* bwd0_b = (const float*)d_in[17];
    const float* bwd1_w = (const float*)d_in[18];
    const float* bwd1_b = (const float*)d_in[19];
    const float* rl0_w  = (const float*)d_in[20];
    const float* rl0_b  = (const float*)d_in[21];
    const float* rl1_w  = (const float*)d_in[22];
    const float* rl1_b  = (const float*)d_in[23];
    const float* cost0_w = (const float*)d_in[24];
    const float* cost0_b = (const float*)d_in[25];
    const float* cost1_w = (const float*)d_in[26];
    const float* cost1_b = (const float*)d_in[27];
    const float* pol_w   = (const float*)d_in[28];
    const float* pol_b   = (const float*)d_in[29];

    const int N = in_sizes[0] / F_IN;
    const int S = out_size;

    static int configured = 0;
    if (!configured) {
        cudaFuncSetAttribute(phaseA_mma,
                             cudaFuncAttributeMaxDynamicSharedMemorySize,
                             SMEM_BYTES);
        configured = 1;
    }

    {
        int n4 = (S_SEG * 64) / 4;
        zero_kernel<<<(n4 + 255) / 256, 256>>>(n4);
    }

    phaseA_mma<<<GRID_A, BLK, SMEM_BYTES>>>(
        x, sid, tfc0_w, tfc0_b, tfc1_w, tfc1_b,
        rl0_w, rl0_b, rl1_w, rl1_b, N);

    phaseB_kernel<<<128, 256>>>(
        fwd0_w, fwd0_b, fwd1_w, fwd1_b,
        com0_w, com0_b, com1_w, com1_b,
        bwd0_w, bwd0_b, bwd1_w, bwd1_b,
        cost0_w, cost0_b, cost1_w, cost1_b,
        pol_w, pol_b,
        (float*)d_out, S);
}